// round 7
// baseline (speedup 1.0000x reference)
#include <cuda_runtime.h>
#include <cuda_bf16.h>
#include <cstdint>

// LayerHypercube: out[b, f*1024+o] = sum_j x[b, o^(1<<j)] * w[f,j,o] + bias[f,o] + x[b,o]
// B=2048, F=16, O=IN=1024, BITS=10. fm[f,j,o] == o^(1<<j) (computed, not loaded).
//
// R7: no smem, no barriers. x gathers via LDG (L1-resident working set).
// j=0,1 register permutations; j=2..5 shfl.bfly; j=6..9 LDG from the 4
// remote 64-float chunks. Packed f32x2 math. Warps fully independent.

#define BATCH   2048
#define INSZ    1024
#define OUTSZ   1024
#define NFM     16
#define NBITS   10

#define THREADS 128
#define OG      16
#define OTILE   64
#define ROWS    32              // 16 pairs per block
#define PAIRS   (ROWS / 2)
#define OBLOCKS (OUTSZ / OTILE) // 16
#define BBLOCKS (BATCH / ROWS)  // 64

typedef unsigned long long ull;

__device__ __forceinline__ void fma2(ull& d, ull a, ull b) {
    asm("fma.rn.f32x2 %0, %1, %2, %0;" : "+l"(d) : "l"(a), "l"(b));
}
__device__ __forceinline__ ull add2(ull a, ull b) {
    ull d; asm("add.rn.f32x2 %0, %1, %2;" : "=l"(d) : "l"(a), "l"(b)); return d;
}
__device__ __forceinline__ ull pk(float lo, float hi) {
    ull d; asm("mov.b64 %0, {%1, %2};" : "=l"(d) : "f"(lo), "f"(hi)); return d;
}
__device__ __forceinline__ void stcs2(void* p, ull lo, ull hi) {
    asm volatile("st.global.cs.v2.b64 [%0], {%1, %2};" :: "l"(p), "l"(lo), "l"(hi));
}

__global__ __launch_bounds__(THREADS, 4)
void hypercube_kernel(const float* __restrict__ x,
                      const float* __restrict__ w,
                      const float* __restrict__ bias,
                      float* __restrict__ out)
{
    const int tid   = threadIdx.x;
    const int og    = tid & (OG - 1);
    const int fp    = tid >> 4;
    const int obase = blockIdx.x * OTILE + og * 4;
    const int row0  = blockIdx.y * ROWS;
    const int B0    = blockIdx.x * OTILE;

    // ---- weights & bias -> registers as f32x2 pairs (88 regs) ----
    ull w0l[NBITS], w0h[NBITS], w1l[NBITS], w1h[NBITS];
#pragma unroll
    for (int j = 0; j < NBITS; j++) {
        ulonglong2 t0 = *reinterpret_cast<const ulonglong2*>(
            w + ((fp * NBITS + j) * OUTSZ + obase));
        ulonglong2 t1 = *reinterpret_cast<const ulonglong2*>(
            w + (((fp + 8) * NBITS + j) * OUTSZ + obase));
        w0l[j] = t0.x; w0h[j] = t0.y;
        w1l[j] = t1.x; w1h[j] = t1.y;
    }
    const ulonglong2 bb0 = *reinterpret_cast<const ulonglong2*>(bias + fp * OUTSZ + obase);
    const ulonglong2 bb1 = *reinterpret_cast<const ulonglong2*>(bias + (fp + 8) * OUTSZ + obase);

    // float4 indices within a row for own + 4 remote gathers
    const int gown = (B0 >> 2) + og;
    const int gr0  = ((B0 ^ 64)  >> 2) + og;
    const int gr1  = ((B0 ^ 128) >> 2) + og;
    const int gr2  = ((B0 ^ 256) >> 2) + og;
    const int gr3  = ((B0 ^ 512) >> 2) + og;

    const float4* xr = reinterpret_cast<const float4*>(x) + (size_t)row0 * (INSZ / 4);
    float* op = out + (size_t)row0 * (NFM * OUTSZ) + fp * OUTSZ + obase;

#pragma unroll 4
    for (int s = 0; s < PAIRS; s++) {
        const float4* A = xr;                    // row 2s
        const float4* Brow = xr + (INSZ / 4);    // row 2s+1

        // Issue all global loads up front (10 LDG.128, independent)
        const float4 p  = A[gown];
        const float4 q  = Brow[gown];
        const float4 u0 = A[gr0], u1 = A[gr1], u2 = A[gr2], u3 = A[gr3];
        const float4 v0 = Brow[gr0], v1 = Brow[gr1], v2 = Brow[gr2], v3 = Brow[gr3];

        const ull Pl = pk(p.x, p.y), Ph = pk(p.z, p.w);
        const ull Ql = pk(q.x, q.y), Qh = pk(q.z, q.w);

        // acc = bias + tiled x
        ull a0l = add2(bb0.x, Pl), a0h = add2(bb0.y, Ph);
        ull a1l = add2(bb1.x, Pl), a1h = add2(bb1.y, Ph);
        ull c0l = add2(bb0.x, Ql), c0h = add2(bb0.y, Qh);
        ull c1l = add2(bb1.x, Ql), c1h = add2(bb1.y, Qh);

        // j=0: x[o^1] -> per-pair swap (free re-pack)
        {
            const ull Psl = pk(p.y, p.x), Psh = pk(p.w, p.z);
            const ull Qsl = pk(q.y, q.x), Qsh = pk(q.w, q.z);
            fma2(a0l, w0l[0], Psl); fma2(a0h, w0h[0], Psh);
            fma2(a1l, w1l[0], Psl); fma2(a1h, w1h[0], Psh);
            fma2(c0l, w0l[0], Qsl); fma2(c0h, w0h[0], Qsh);
            fma2(c1l, w1l[0], Qsl); fma2(c1h, w1h[0], Qsh);
        }

        // j=1: x[o^2] -> half reversal (operand order, free)
        fma2(a0l, w0l[1], Ph);  fma2(a0h, w0h[1], Pl);
        fma2(a1l, w1l[1], Ph);  fma2(a1h, w1h[1], Pl);
        fma2(c0l, w0l[1], Qh);  fma2(c0h, w0h[1], Ql);
        fma2(c1l, w1l[1], Qh);  fma2(c1h, w1h[1], Ql);

        // j=2..5: partner lane (lane^m, m=1,2,4,8) holds x[o^(4<<k)] -> shfl.bfly
#pragma unroll
        for (int k = 0; k < 4; k++) {
            const int m = 1 << k;
            const int j = k + 2;
            const float ux = __shfl_xor_sync(0xffffffffu, p.x, m);
            const float uy = __shfl_xor_sync(0xffffffffu, p.y, m);
            const float uz = __shfl_xor_sync(0xffffffffu, p.z, m);
            const float uw = __shfl_xor_sync(0xffffffffu, p.w, m);
            const float vx = __shfl_xor_sync(0xffffffffu, q.x, m);
            const float vy = __shfl_xor_sync(0xffffffffu, q.y, m);
            const float vz = __shfl_xor_sync(0xffffffffu, q.z, m);
            const float vw = __shfl_xor_sync(0xffffffffu, q.w, m);
            const ull Ulo = pk(ux, uy), Uhi = pk(uz, uw);
            const ull Vlo = pk(vx, vy), Vhi = pk(vz, vw);
            fma2(a0l, w0l[j], Ulo); fma2(a0h, w0h[j], Uhi);
            fma2(a1l, w1l[j], Ulo); fma2(a1h, w1h[j], Uhi);
            fma2(c0l, w0l[j], Vlo); fma2(c0h, w0h[j], Vhi);
            fma2(c1l, w1l[j], Vlo); fma2(c1h, w1h[j], Vhi);
        }

        // j=6..9: remote-chunk gathers (already loaded above)
        {
            const ull U0l = pk(u0.x, u0.y), U0h = pk(u0.z, u0.w);
            const ull V0l = pk(v0.x, v0.y), V0h = pk(v0.z, v0.w);
            fma2(a0l, w0l[6], U0l); fma2(a0h, w0h[6], U0h);
            fma2(a1l, w1l[6], U0l); fma2(a1h, w1h[6], U0h);
            fma2(c0l, w0l[6], V0l); fma2(c0h, w0h[6], V0h);
            fma2(c1l, w1l[6], V0l); fma2(c1h, w1h[6], V0h);

            const ull U1l = pk(u1.x, u1.y), U1h = pk(u1.z, u1.w);
            const ull V1l = pk(v1.x, v1.y), V1h = pk(v1.z, v1.w);
            fma2(a0l, w0l[7], U1l); fma2(a0h, w0h[7], U1h);
            fma2(a1l, w1l[7], U1l); fma2(a1h, w1h[7], U1h);
            fma2(c0l, w0l[7], V1l); fma2(c0h, w0h[7], V1h);
            fma2(c1l, w1l[7], V1l); fma2(c1h, w1h[7], V1h);

            const ull U2l = pk(u2.x, u2.y), U2h = pk(u2.z, u2.w);
            const ull V2l = pk(v2.x, v2.y), V2h = pk(v2.z, v2.w);
            fma2(a0l, w0l[8], U2l); fma2(a0h, w0h[8], U2h);
            fma2(a1l, w1l[8], U2l); fma2(a1h, w1h[8], U2h);
            fma2(c0l, w0l[8], V2l); fma2(c0h, w0h[8], V2h);
            fma2(c1l, w1l[8], V2l); fma2(c1h, w1h[8], V2h);

            const ull U3l = pk(u3.x, u3.y), U3h = pk(u3.z, u3.w);
            const ull V3l = pk(v3.x, v3.y), V3h = pk(v3.z, v3.w);
            fma2(a0l, w0l[9], U3l); fma2(a0h, w0h[9], U3h);
            fma2(a1l, w1l[9], U3l); fma2(a1h, w1h[9], U3h);
            fma2(c0l, w0l[9], V3l); fma2(c0h, w0h[9], V3h);
            fma2(c1l, w1l[9], V3l); fma2(c1h, w1h[9], V3h);
        }

        stcs2(op,                           a0l, a0h);
        stcs2(op + 8 * OUTSZ,               a1l, a1h);
        stcs2(op + NFM * OUTSZ,             c0l, c0h);
        stcs2(op + NFM * OUTSZ + 8 * OUTSZ, c1l, c1h);

        op += 2 * NFM * OUTSZ;
        xr += 2 * (INSZ / 4);
    }
}

extern "C" void kernel_launch(void* const* d_in, const int* in_sizes, int n_in,
                              void* d_out, int out_size)
{
    const float* x    = (const float*)d_in[0];
    const float* w    = (const float*)d_in[1];
    const float* bias = (const float*)d_in[2];
    // d_in[3] = fm (int32) — values are o^(1<<j), computed inline instead.
    float* out = (float*)d_out;

    dim3 grid(OBLOCKS, BBLOCKS);
    hypercube_kernel<<<grid, THREADS>>>(x, w, bias, out);
}

// round 8
// speedup vs baseline: 1.3161x; 1.3161x over previous
#include <cuda_runtime.h>
#include <cuda_bf16.h>
#include <cstdint>

// LayerHypercube: out[b, f*1024+o] = sum_j x[b, o^(1<<j)] * w[f,j,o] + bias[f,o] + x[b,o]
// B=2048, F=16, O=IN=1024, BITS=10. fm[f,j,o] == o^(1<<j) (computed, not loaded).
//
// R8: warp-private smem staging (each warp stages its own 5-chunk row pair),
// cp.async wait is per-warp -> NO __syncthreads anywhere. j=0,1 register
// permutations; j=2..5 shfl.bfly; j=6..9 LDS from warp's own buffer.

#define BATCH   2048
#define INSZ    1024
#define OUTSZ   1024
#define NFM     16
#define NBITS   10

#define THREADS 128
#define NWARP   4
#define OG      16
#define OTILE   64
#define ROWS    32              // 16 pairs per block
#define PAIRS   (ROWS / 2)
#define OBLOCKS (OUTSZ / OTILE) // 16
#define BBLOCKS (BATCH / ROWS)  // 64
#define NBUF    3

#define CHUNK_B   256
#define ROW_B     (5 * CHUNK_B)     // 1280 bytes per row (5 chunks)
#define WBUF_B    (2 * ROW_B)       // 2560 bytes per warp-buffer (pair)

typedef unsigned long long ull;

__device__ __forceinline__ void cp16(uint32_t dst_smem, const void* src_gmem) {
    asm volatile("cp.async.cg.shared.global [%0], [%1], 16;\n"
                 :: "r"(dst_smem), "l"(src_gmem));
}
__device__ __forceinline__ void cp_commit() { asm volatile("cp.async.commit_group;\n"); }
__device__ __forceinline__ void cp_wait1()  { asm volatile("cp.async.wait_group 1;\n"); }

__device__ __forceinline__ void fma2(ull& d, ull a, ull b) {
    asm("fma.rn.f32x2 %0, %1, %2, %0;" : "+l"(d) : "l"(a), "l"(b));
}
__device__ __forceinline__ ull add2(ull a, ull b) {
    ull d; asm("add.rn.f32x2 %0, %1, %2;" : "=l"(d) : "l"(a), "l"(b)); return d;
}
__device__ __forceinline__ ull pk(float lo, float hi) {
    ull d; asm("mov.b64 %0, {%1, %2};" : "=l"(d) : "f"(lo), "f"(hi)); return d;
}
__device__ __forceinline__ void stcs2(void* p, ull lo, ull hi) {
    asm volatile("st.global.cs.v2.b64 [%0], {%1, %2};" :: "l"(p), "l"(lo), "l"(hi));
}

__global__ __launch_bounds__(THREADS, 4)
void hypercube_kernel(const float* __restrict__ x,
                      const float* __restrict__ w,
                      const float* __restrict__ bias,
                      float* __restrict__ out)
{
    __shared__ float4 sbuf[NBUF * NWARP * (WBUF_B / 16)];   // 30720 B

    const int tid   = threadIdx.x;
    const int lane  = tid & 31;
    const int wid   = tid >> 5;
    const int og    = tid & (OG - 1);
    const int fp    = tid >> 4;
    const int obase = blockIdx.x * OTILE + og * 4;
    const int row0  = blockIdx.y * ROWS;
    const int B0    = blockIdx.x * OTILE;

    // ---- weights & bias -> registers as f32x2 pairs ----
    ull w0l[NBITS], w0h[NBITS], w1l[NBITS], w1h[NBITS];
#pragma unroll
    for (int j = 0; j < NBITS; j++) {
        ulonglong2 t0 = *reinterpret_cast<const ulonglong2*>(
            w + ((fp * NBITS + j) * OUTSZ + obase));
        ulonglong2 t1 = *reinterpret_cast<const ulonglong2*>(
            w + (((fp + 8) * NBITS + j) * OUTSZ + obase));
        w0l[j] = t0.x; w0h[j] = t0.y;
        w1l[j] = t1.x; w1h[j] = t1.y;
    }
    const ulonglong2 bb0 = *reinterpret_cast<const ulonglong2*>(bias + fp * OUTSZ + obase);
    const ulonglong2 bb1 = *reinterpret_cast<const ulonglong2*>(bias + (fp + 8) * OUTSZ + obase);

    // ---- warp-private staging: 160 16B units per pair, 5 per lane ----
    // unit u = k*32 + lane; dst byte = u*16 (contiguous); src irregular.
    int srcOff[5];
    {
        const int tb = B0 * 4;   // tile byte offset within a row
#pragma unroll
        for (int k = 0; k < 5; k++) {
            const int u = k * 32 + lane;
            const int r = (u >= 80) ? 1 : 0;
            const int t = u - 80 * r;
            const int c = t >> 4;
            const int i = t & 15;
            const int xorB = (c == 0) ? 0 : (256 << (c - 1));  // 0,256,512,1024,2048
            srcOff[k] = r * 4096 + (tb ^ xorB) + i * 16;
        }
    }

    // warp's buffer n base address (bytes): sbase + (n*NWARP + wid)*WBUF_B
    const uint32_t wb0 = (uint32_t)__cvta_generic_to_shared(sbuf) + wid * WBUF_B;
    const char*    xpb = reinterpret_cast<const char*>(x + (size_t)row0 * INSZ);

    auto issue_pair = [&](int bufIdx, int pair) {
        const char* base = xpb + (size_t)pair * 8192;
        const uint32_t db = wb0 + bufIdx * (NWARP * WBUF_B) + lane * 16;
#pragma unroll
        for (int k = 0; k < 5; k++)
            cp16(db + k * 512, base + srcOff[k]);
    };

    issue_pair(0, 0); cp_commit();
    issue_pair(1, 1); cp_commit();

    float* op = out + (size_t)row0 * (NFM * OUTSZ) + fp * OUTSZ + obase;

    int cur = 0;
    for (int s = 0; s < PAIRS; s++) {
        cp_wait1();                       // warp-local: pair s landed

        int nxt = cur + 2; if (nxt >= NBUF) nxt -= NBUF;
        if (s + 2 < PAIRS) issue_pair(nxt, s + 2);
        cp_commit();

        const float4* rbA = sbuf + (cur * NWARP + wid) * (WBUF_B / 16);
        const float4* rbB = rbA + (ROW_B / 16);

        const float4 p = rbA[og];
        const float4 q = rbB[og];
        const ull Pl = pk(p.x, p.y), Ph = pk(p.z, p.w);
        const ull Ql = pk(q.x, q.y), Qh = pk(q.z, q.w);

        // acc = bias + tiled x
        ull a0l = add2(bb0.x, Pl), a0h = add2(bb0.y, Ph);
        ull a1l = add2(bb1.x, Pl), a1h = add2(bb1.y, Ph);
        ull c0l = add2(bb0.x, Ql), c0h = add2(bb0.y, Qh);
        ull c1l = add2(bb1.x, Ql), c1h = add2(bb1.y, Qh);

        // j=0: x[o^1] -> per-pair swap (free re-pack)
        {
            const ull Psl = pk(p.y, p.x), Psh = pk(p.w, p.z);
            const ull Qsl = pk(q.y, q.x), Qsh = pk(q.w, q.z);
            fma2(a0l, w0l[0], Psl); fma2(a0h, w0h[0], Psh);
            fma2(a1l, w1l[0], Psl); fma2(a1h, w1h[0], Psh);
            fma2(c0l, w0l[0], Qsl); fma2(c0h, w0h[0], Qsh);
            fma2(c1l, w1l[0], Qsl); fma2(c1h, w1h[0], Qsh);
        }

        // j=1: x[o^2] -> half reversal (operand order, free)
        fma2(a0l, w0l[1], Ph);  fma2(a0h, w0h[1], Pl);
        fma2(a1l, w1l[1], Ph);  fma2(a1h, w1h[1], Pl);
        fma2(c0l, w0l[1], Qh);  fma2(c0h, w0h[1], Ql);
        fma2(c1l, w1l[1], Qh);  fma2(c1h, w1h[1], Ql);

        // j=2..5: partner lane (lane^m, m=1,2,4,8) holds x[o^(4<<k)] -> shfl.bfly
#pragma unroll
        for (int k = 0; k < 4; k++) {
            const int m = 1 << k;
            const int j = k + 2;
            const float ux = __shfl_xor_sync(0xffffffffu, p.x, m);
            const float uy = __shfl_xor_sync(0xffffffffu, p.y, m);
            const float uz = __shfl_xor_sync(0xffffffffu, p.z, m);
            const float uw = __shfl_xor_sync(0xffffffffu, p.w, m);
            const float vx = __shfl_xor_sync(0xffffffffu, q.x, m);
            const float vy = __shfl_xor_sync(0xffffffffu, q.y, m);
            const float vz = __shfl_xor_sync(0xffffffffu, q.z, m);
            const float vw = __shfl_xor_sync(0xffffffffu, q.w, m);
            const ull Ulo = pk(ux, uy), Uhi = pk(uz, uw);
            const ull Vlo = pk(vx, vy), Vhi = pk(vz, vw);
            fma2(a0l, w0l[j], Ulo); fma2(a0h, w0h[j], Uhi);
            fma2(a1l, w1l[j], Ulo); fma2(a1h, w1h[j], Uhi);
            fma2(c0l, w0l[j], Vlo); fma2(c0h, w0h[j], Vhi);
            fma2(c1l, w1l[j], Vlo); fma2(c1h, w1h[j], Vhi);
        }

        // j=6..9: LDS gathers from chunks 1..4 at the SAME og (warp-own buffer)
#pragma unroll
        for (int j = 6; j < NBITS; j++) {
            const int gi = (j - 5) * 16 + og;
            const ulonglong2 U = *reinterpret_cast<const ulonglong2*>(&rbA[gi]);
            const ulonglong2 V = *reinterpret_cast<const ulonglong2*>(&rbB[gi]);
            fma2(a0l, w0l[j], U.x); fma2(a0h, w0h[j], U.y);
            fma2(a1l, w1l[j], U.x); fma2(a1h, w1h[j], U.y);
            fma2(c0l, w0l[j], V.x); fma2(c0h, w0h[j], V.y);
            fma2(c1l, w1l[j], V.x); fma2(c1h, w1h[j], V.y);
        }

        stcs2(op,                           a0l, a0h);
        stcs2(op + 8 * OUTSZ,               a1l, a1h);
        stcs2(op + NFM * OUTSZ,             c0l, c0h);
        stcs2(op + NFM * OUTSZ + 8 * OUTSZ, c1l, c1h);

        op += 2 * NFM * OUTSZ;
        cur = cur + 1; if (cur >= NBUF) cur -= NBUF;
    }
}

extern "C" void kernel_launch(void* const* d_in, const int* in_sizes, int n_in,
                              void* d_out, int out_size)
{
    const float* x    = (const float*)d_in[0];
    const float* w    = (const float*)d_in[1];
    const float* bias = (const float*)d_in[2];
    // d_in[3] = fm (int32) — values are o^(1<<j), computed inline instead.
    float* out = (float*)d_out;

    dim3 grid(OBLOCKS, BBLOCKS);
    hypercube_kernel<<<grid, THREADS>>>(x, w, bias, out);
}